// round 1
// baseline (speedup 1.0000x reference)
#include <cuda_runtime.h>

// Fully fused quantized CIFAR-10 net. One CTA per image, all intermediates in SMEM.
// All quantized values are exactly representable; accumulations are exact in fp32,
// so the result is bit-exact vs the JAX reference (rintf == round-half-even == jnp.round).

#define THREADS 256
#define SMEM_BYTES 90112

__device__ __forceinline__ float clampf(float x, float lo, float hi) {
    return fmaxf(lo, fminf(hi, x));
}
// weight fake-quant, 4-bit signed, scale 0.25 -> dequantized value
__device__ __forceinline__ float qw4(float w) { return clampf(rintf(w * 4.f), -8.f, 7.f) * 0.25f; }
// weight fake-quant, 8-bit signed, scale 0.25
__device__ __forceinline__ float qw8(float w) { return clampf(rintf(w * 4.f), -128.f, 127.f) * 0.25f; }
// activation fake-quant, 4-bit signed, scale 0.5
__device__ __forceinline__ float qa4(float x) { return clampf(rintf(x * 2.f), -8.f, 7.f) * 0.5f; }
// activation fake-quant, 8-bit signed, scale 2^-4
__device__ __forceinline__ float qa8(float x) { return clampf(rintf(x * 16.f), -128.f, 127.f) * 0.0625f; }
// QuantReLU 4-bit unsigned, scale 0.25 -> integer code in [0,15]
__device__ __forceinline__ float relucode(float x) { return fminf(rintf(fmaxf(x, 0.f) * 4.f), 15.f); }
// map relu code (value = code*0.25) through 4-bit signed S_ACT4 quant -> dequant value
__device__ __forceinline__ float code2act4(float c) { return fminf(rintf(c * 0.5f), 7.f) * 0.5f; }

__global__ __launch_bounds__(THREADS, 2)
void qnet_kernel(const float* __restrict__ x,
                 const float* __restrict__ w0,  const float* __restrict__ dw1,
                 const float* __restrict__ pw1, const float* __restrict__ dw2,
                 const float* __restrict__ pw2, const float* __restrict__ dw3,
                 const float* __restrict__ pw3, const float* __restrict__ wc1,
                 const float* __restrict__ wc2, float* __restrict__ out)
{
    extern __shared__ unsigned char sm[];
    // ---- overlapped stage-local regions (byte offsets) ----
    float*         A    = (float*)(sm + 0);      // 3*1024 f32   [0,12288)
    float*         B    = (float*)(sm + 12288);  // 3*1024 f32   [12288,24576)
    unsigned char* C    = sm + 24576;            // 32*1024 u8   [24576,57344)
    unsigned char* D    = sm + 0;                // 32*256 u8    [0,8192)
    float*         E    = (float*)(sm + 8192);   // 32*256 f32   [8192,40960)
    float*         F    = (float*)(sm + 40960);  // 32*256 f32   [40960,73728)
    float*         Wpw2 = (float*)(sm + 16384);  // 64*32 f32    [16384,24576)
    unsigned char* G    = sm + 0;                // 64*256 u8    [0,16384)
    unsigned char* H    = sm + 16384;            // 64*64 u8     [16384,20480)
    float*         Ib   = (float*)(sm + 20480);  // 64*64 f32    [20480,36864)
    float*         J    = (float*)(sm + 36864);  // 64*64 f32    [36864,53248)
    float*         Wpw3 = (float*)(sm + 53248);  // 128*64 f32   [53248,86016)
    unsigned char* K    = sm + 0;                // 128*64 u8    [0,8192)
    float*         V    = (float*)(sm + 8448);   // 128 f32      [8448,8960)
    float*         V2   = (float*)(sm + 9216);   // 256 f32      [9216,10240)
    signed char*   Wfc1 = (signed char*)(sm + 12288); // 128*256 i8 transposed [ic][oc]
    float*         Wfc2 = (float*)(sm + 45056);  // 10*256 f32   [45056,55296)
    float*         WS   = (float*)(sm + 86016);  // small weights: 996 f32

    const int tid = threadIdx.x;
    const int b   = blockIdx.x;

    // ---- stage small weights (quantize-dequantize once) ----
    // WS: w0q[0..9) dw1q[9..36) pw1q[36..132) dw2q[132..420) dw3q[420..996)
    for (int i = tid; i < 9;   i += THREADS) WS[i]       = qw8(w0[i]);
    for (int i = tid; i < 27;  i += THREADS) WS[9 + i]   = qw4(dw1[i]);
    for (int i = tid; i < 96;  i += THREADS) WS[36 + i]  = qw4(pw1[i]);
    for (int i = tid; i < 288; i += THREADS) WS[132 + i] = qw4(dw2[i]);
    for (int i = tid; i < 576; i += THREADS) WS[420 + i] = qw4(dw3[i]);

    // ---- load + 8-bit quant input ----
    const float* xin = x + (size_t)b * 3072;
    for (int i = tid; i < 3072; i += THREADS) A[i] = qa8(xin[i]);
    __syncthreads();

    // ---- conv0: 1x1, 3->3 (8-bit), then 4-bit input quant for dw1 ----
    for (int p = tid; p < 1024; p += THREADS) {
        float a0 = A[p], a1 = A[1024 + p], a2 = A[2048 + p];
        #pragma unroll
        for (int oc = 0; oc < 3; oc++) {
            float o = WS[oc * 3 + 0] * a0 + WS[oc * 3 + 1] * a1 + WS[oc * 3 + 2] * a2;
            B[oc * 1024 + p] = qa4(o);
        }
    }
    __syncthreads();

    // ---- dw1: depthwise 3x3 pad 1, 3ch @32x32, then 4-bit quant ----
    for (int i = tid; i < 3072; i += THREADS) {
        int c = i >> 10, p = i & 1023, y = p >> 5, xx = p & 31;
        const float* wp = WS + 9 + c * 9;
        const float* bp = B + c * 1024;
        float t = 0.f;
        #pragma unroll
        for (int ky = 0; ky < 3; ky++) {
            int yy = y + ky - 1;
            if (yy < 0 || yy > 31) continue;
            #pragma unroll
            for (int kx = 0; kx < 3; kx++) {
                int xc = xx + kx - 1;
                if (xc < 0 || xc > 31) continue;
                t += bp[yy * 32 + xc] * wp[ky * 3 + kx];
            }
        }
        A[i] = qa4(t);
    }
    __syncthreads();

    // ---- pw1: 1x1, 3->32 @32x32 + QuantReLU4 -> codes ----
    for (int i = tid; i < 32768; i += THREADS) {
        int oc = i >> 10, p = i & 1023;
        float o = A[p] * WS[36 + oc * 3] + A[1024 + p] * WS[36 + oc * 3 + 1]
                + A[2048 + p] * WS[36 + oc * 3 + 2];
        C[i] = (unsigned char)relucode(o);
    }
    __syncthreads();

    // ---- maxpool 2x2: 32x32 -> 16x16 (on codes; quant is monotonic) ----
    for (int i = tid; i < 8192; i += THREADS) {
        int oc = i >> 8, p = i & 255, y = p >> 4, xx = p & 15;
        const unsigned char* bp = C + oc * 1024 + (y * 2) * 32 + xx * 2;
        int m = max(max((int)bp[0], (int)bp[1]), max((int)bp[32], (int)bp[33]));
        D[i] = (unsigned char)m;
    }
    __syncthreads();

    // ---- dw2 input: dequant code, requant 4-bit signed ----
    for (int i = tid; i < 8192; i += THREADS) E[i] = code2act4((float)D[i]);
    __syncthreads();

    // ---- dw2: depthwise 3x3 pad 1, 32ch @16x16, quant -> F ----
    for (int i = tid; i < 8192; i += THREADS) {
        int c = i >> 8, p = i & 255, y = p >> 4, xx = p & 15;
        const float* wp = WS + 132 + c * 9;
        const float* ep = E + c * 256;
        float t = 0.f;
        #pragma unroll
        for (int ky = 0; ky < 3; ky++) {
            int yy = y + ky - 1;
            if (yy < 0 || yy > 15) continue;
            #pragma unroll
            for (int kx = 0; kx < 3; kx++) {
                int xc = xx + kx - 1;
                if (xc < 0 || xc > 15) continue;
                t += ep[yy * 16 + xc] * wp[ky * 3 + kx];
            }
        }
        F[i] = qa4(t);
    }
    __syncthreads();   // E dead from here; Wpw2 may overwrite it

    for (int i = tid; i < 2048; i += THREADS) Wpw2[i] = qw4(pw2[i]);
    __syncthreads();

    // ---- pw2: 1x1, 32->64 @16x16 + QuantReLU4. 4oc x 4px register blocking ----
    for (int t2 = tid; t2 < 1024; t2 += THREADS) {
        int ocb = t2 >> 6, pb = t2 & 63;
        int oc0 = ocb * 4, p0 = pb * 4;
        float acc[4][4] = {};
        for (int ic = 0; ic < 32; ic++) {
            float4 a = *(const float4*)(F + ic * 256 + p0);
            #pragma unroll
            for (int i2 = 0; i2 < 4; i2++) {
                float w = Wpw2[(oc0 + i2) * 32 + ic];
                acc[i2][0] += w * a.x; acc[i2][1] += w * a.y;
                acc[i2][2] += w * a.z; acc[i2][3] += w * a.w;
            }
        }
        #pragma unroll
        for (int i2 = 0; i2 < 4; i2++)
            #pragma unroll
            for (int j = 0; j < 4; j++)
                G[(oc0 + i2) * 256 + p0 + j] = (unsigned char)relucode(acc[i2][j]);
    }
    __syncthreads();

    // ---- maxpool 2x2: 16x16 -> 8x8 ; also stage Wpw3 (region free) ----
    for (int i = tid; i < 4096; i += THREADS) {
        int oc = i >> 6, p = i & 63, y = p >> 3, xx = p & 7;
        const unsigned char* bp = G + oc * 256 + (y * 2) * 16 + xx * 2;
        int m = max(max((int)bp[0], (int)bp[1]), max((int)bp[16], (int)bp[17]));
        H[i] = (unsigned char)m;
    }
    for (int i = tid; i < 8192; i += THREADS) Wpw3[i] = qw4(pw3[i]);
    __syncthreads();

    // ---- dw3 input requant ----
    for (int i = tid; i < 4096; i += THREADS) Ib[i] = code2act4((float)H[i]);
    __syncthreads();

    // ---- dw3: depthwise 3x3 pad 1, 64ch @8x8, quant -> J ----
    for (int i = tid; i < 4096; i += THREADS) {
        int c = i >> 6, p = i & 63, y = p >> 3, xx = p & 7;
        const float* wp = WS + 420 + c * 9;
        const float* ip = Ib + c * 64;
        float t = 0.f;
        #pragma unroll
        for (int ky = 0; ky < 3; ky++) {
            int yy = y + ky - 1;
            if (yy < 0 || yy > 7) continue;
            #pragma unroll
            for (int kx = 0; kx < 3; kx++) {
                int xc = xx + kx - 1;
                if (xc < 0 || xc > 7) continue;
                t += ip[yy * 8 + xc] * wp[ky * 3 + kx];
            }
        }
        J[i] = qa4(t);
    }
    __syncthreads();

    // ---- pw3: 1x1, 64->128 @8x8 + QuantReLU4. 4oc x 4px blocking ----
    for (int t2 = tid; t2 < 512; t2 += THREADS) {
        int ocb = t2 >> 4, pb = t2 & 15;
        int oc0 = ocb * 4, p0 = pb * 4;
        float acc[4][4] = {};
        for (int ic = 0; ic < 64; ic++) {
            float4 a = *(const float4*)(J + ic * 64 + p0);
            #pragma unroll
            for (int i2 = 0; i2 < 4; i2++) {
                float w = Wpw3[(oc0 + i2) * 64 + ic];
                acc[i2][0] += w * a.x; acc[i2][1] += w * a.y;
                acc[i2][2] += w * a.z; acc[i2][3] += w * a.w;
            }
        }
        #pragma unroll
        for (int i2 = 0; i2 < 4; i2++)
            #pragma unroll
            for (int j = 0; j < 4; j++)
                K[(oc0 + i2) * 64 + p0 + j] = (unsigned char)relucode(acc[i2][j]);
    }
    __syncthreads();

    // ---- global maxpool 8x8 -> 1x1, then classifier input quant ----
    if (tid < 128) {
        const unsigned char* kp = K + tid * 64;
        int m = 0;
        #pragma unroll 8
        for (int p = 0; p < 64; p++) m = max(m, (int)kp[p]);
        V[tid] = code2act4((float)m);
    }
    __syncthreads();

    // ---- stage fc weights: wc1 as transposed int8 [ic][oc], wc2 as float ----
    for (int i = tid; i < 32768; i += THREADS) {
        int oc = i >> 7, ic = i & 127;
        float q = clampf(rintf(wc1[i] * 4.f), -8.f, 7.f);
        Wfc1[ic * 256 + oc] = (signed char)q;
    }
    for (int i = tid; i < 2560; i += THREADS) Wfc2[i] = qw4(wc2[i]);
    __syncthreads();

    // ---- fc1: 128 -> 256 (4-bit), + QuantReLU4, + fc2 input quant ----
    {
        float acc = 0.f;
        #pragma unroll 4
        for (int ic = 0; ic < 128; ic++)
            acc += V[ic] * ((float)Wfc1[ic * 256 + tid] * 0.25f);
        V2[tid] = code2act4(relucode(acc));
    }
    __syncthreads();

    // ---- fc2: 256 -> 10 (4-bit), output 8-bit quant ----
    if (tid < 160) {
        int oc = tid >> 4, l = tid & 15;
        const float* wp = Wfc2 + oc * 256;
        float acc = 0.f;
        #pragma unroll 4
        for (int ic = l; ic < 256; ic += 16) acc += V2[ic] * wp[ic];
        #pragma unroll
        for (int off = 8; off; off >>= 1) acc += __shfl_down_sync(0xffffffffu, acc, off, 16);
        if (l == 0)
            out[(size_t)b * 10 + oc] = clampf(rintf(acc * 16.f), -128.f, 127.f) * 0.0625f;
    }
}

extern "C" void kernel_launch(void* const* d_in, const int* in_sizes, int n_in,
                              void* d_out, int out_size)
{
    (void)in_sizes; (void)n_in; (void)out_size;
    const float* x   = (const float*)d_in[0];
    const float* w0  = (const float*)d_in[1];
    const float* dw1 = (const float*)d_in[2];
    const float* pw1 = (const float*)d_in[3];
    const float* dw2 = (const float*)d_in[4];
    const float* pw2 = (const float*)d_in[5];
    const float* dw3 = (const float*)d_in[6];
    const float* pw3 = (const float*)d_in[7];
    const float* wc1 = (const float*)d_in[8];
    const float* wc2 = (const float*)d_in[9];
    float* out = (float*)d_out;

    static bool attr_set = false;
    // cudaFuncSetAttribute is idempotent host-side configuration (not a stream op);
    // safe under graph capture. Call unconditionally to stay deterministic.
    cudaFuncSetAttribute(qnet_kernel, cudaFuncAttributeMaxDynamicSharedMemorySize, SMEM_BYTES);
    (void)attr_set;

    qnet_kernel<<<1024, THREADS, SMEM_BYTES>>>(x, w0, dw1, pw1, dw2, pw2, dw3, pw3,
                                               wc1, wc2, out);
}

// round 2
// speedup vs baseline: 4.2653x; 4.2653x over previous
#include <cuda_runtime.h>
#include <cstdint>

// Fully fused quantized CIFAR-10 net, integer/DP4A datapath.
// Prep kernel quantizes+packs all weights once into __device__ globals;
// main kernel: one CTA per image, all intermediates as int4/int8 codes in SMEM.
// All rounding is integer round-half-even == jnp.round ==> bit-exact vs reference.

#define THREADS 256

// ---------------- packed weight globals (written by prep_kernel) ----------------
__device__ uint32_t gW0[4];      // conv0: [oc<3] packed (3 x int8 code, 0)
__device__ uint32_t gPW1[32];    // pw1:   [oc]   packed (3 x int4 code, 0)
__device__ uint32_t gPW2[512];   // pw2:   [oc*8+g]   4 ic codes
__device__ uint32_t gPW3[2048];  // pw3:   [oc*16+g]  4 ic codes
__device__ uint32_t gFC1[8192];  // fc1:   [g*256+oc] 4 ic codes (coalesced by oc)
__device__ uint32_t gFC2[640];   // fc2:   [oc*64+g]  4 ic codes
__device__ signed char gDW1[32];  // 27 used
__device__ signed char gDW2[288];
__device__ signed char gDW3[576];

// ---------------- helpers ----------------
__device__ __forceinline__ int clampi(int v, int lo, int hi) { return min(max(v, lo), hi); }
__device__ __forceinline__ uint32_t pack4(int a, int b, int c, int d) {
    return (uint32_t)(a & 0xFF) | ((uint32_t)(b & 0xFF) << 8) |
           ((uint32_t)(c & 0xFF) << 16) | ((uint32_t)(d & 0xFF) << 24);
}
// weight quant codes
__device__ __forceinline__ int qw4c(float w) {
    float q = rintf(w * 4.f); return (int)fmaxf(-8.f, fminf(7.f, q));
}
__device__ __forceinline__ int qw8c(float w) {
    float q = rintf(w * 4.f); return (int)fmaxf(-128.f, fminf(127.f, q));
}
// activation 8-bit input quant code
__device__ __forceinline__ int qa8c(float v) {
    float q = rintf(v * 16.f); return (int)fmaxf(-128.f, fminf(127.f, q));
}
// integer round-half-even of S/4 (dw/pw act4 requant: round(S*0.25))
__device__ __forceinline__ int rq2(int S) {
    int q = S >> 2, r = S & 3; return q + (r > 2) + ((r == 2) & (q & 1));
}
// integer round-half-even of S/32 (conv0 act4 requant)
__device__ __forceinline__ int rq5(int S) {
    int q = S >> 5, r = S & 31; return q + (r > 16) + ((r == 16) & (q & 1));
}
// QuantReLU4 code from raw int accum (o = S*0.125, code = round(o*4) clip[0,15])
__device__ __forceinline__ int reluc(int S) {
    int m = max(S, 0); int k = m >> 1; k += (k & m & 1); return min(k, 15);
}
// relu code (val c*0.25) -> S_ACT4 signed-4-bit code (round(c*0.5) clip 7)
__device__ __forceinline__ int c2a4(int c) {
    int k = c >> 1; k += (k & c & 1); return min(k, 7);
}

// ---------------- prep: quantize + pack weights ----------------
__global__ void prep_kernel(const float* __restrict__ w0,  const float* __restrict__ dw1,
                            const float* __restrict__ pw1, const float* __restrict__ dw2,
                            const float* __restrict__ pw2, const float* __restrict__ dw3,
                            const float* __restrict__ pw3, const float* __restrict__ wc1,
                            const float* __restrict__ wc2)
{
    int t = blockIdx.x * blockDim.x + threadIdx.x;
    int NT = gridDim.x * blockDim.x;
    for (int i = t; i < 3; i += NT)
        gW0[i] = pack4(qw8c(w0[i*3]), qw8c(w0[i*3+1]), qw8c(w0[i*3+2]), 0);
    for (int i = t; i < 32; i += NT)
        gPW1[i] = pack4(qw4c(pw1[i*3]), qw4c(pw1[i*3+1]), qw4c(pw1[i*3+2]), 0);
    for (int i = t; i < 512; i += NT) {
        int oc = i >> 3, g = i & 7; const float* p = pw2 + oc*32 + g*4;
        gPW2[i] = pack4(qw4c(p[0]), qw4c(p[1]), qw4c(p[2]), qw4c(p[3]));
    }
    for (int i = t; i < 2048; i += NT) {
        int oc = i >> 4, g = i & 15; const float* p = pw3 + oc*64 + g*4;
        gPW3[i] = pack4(qw4c(p[0]), qw4c(p[1]), qw4c(p[2]), qw4c(p[3]));
    }
    for (int i = t; i < 8192; i += NT) {
        int g = i >> 8, oc = i & 255; const float* p = wc1 + oc*128 + g*4;
        gFC1[i] = pack4(qw4c(p[0]), qw4c(p[1]), qw4c(p[2]), qw4c(p[3]));
    }
    for (int i = t; i < 640; i += NT) {
        int oc = i / 64, g = i & 63; const float* p = wc2 + oc*256 + g*4;
        gFC2[i] = pack4(qw4c(p[0]), qw4c(p[1]), qw4c(p[2]), qw4c(p[3]));
    }
    for (int i = t; i < 27;  i += NT) gDW1[i] = (signed char)qw4c(dw1[i]);
    for (int i = t; i < 288; i += NT) gDW2[i] = (signed char)qw4c(dw2[i]);
    for (int i = t; i < 576; i += NT) gDW3[i] = (signed char)qw4c(dw3[i]);
}

// ---------------- main fused kernel ----------------
// SMEM layout (27664 bytes):
//  [0,4096)      A4 (input packed)   -> D (32x256 codes, 8KB spans [0,8192)) -> D3 (4KB) -> Vb/V2b
//  [4096,7168)   B (conv0 out codes) -> P3 at [4096,8192)
//  [8192,16384)  P1 (4KB) -> P2 (8KB) -> K (8KB)
//  [16384,18432) PW2w  [18432,26624) PW3w
//  [26624,26640) W0w   [26640,26768) PW1w
//  [26768,26800) DW1   [26800,27088) DW2   [27088,27664) DW3
#define SM_BYTES 27664

__global__ __launch_bounds__(THREADS, 4)
void qnet_kernel(const float* __restrict__ x, float* __restrict__ out)
{
    extern __shared__ unsigned char sm[];
    const int tid = threadIdx.x;
    const int b   = blockIdx.x;

    uint32_t*      A4   = (uint32_t*)(sm);
    signed char*   B    = (signed char*)(sm + 4096);
    uint32_t*      P1   = (uint32_t*)(sm + 8192);
    signed char*   D    = (signed char*)(sm);
    uint32_t*      P2   = (uint32_t*)(sm + 8192);
    signed char*   D3   = (signed char*)(sm);
    uint32_t*      P3   = (uint32_t*)(sm + 4096);
    unsigned char* K    = (unsigned char*)(sm + 8192);
    unsigned char* Vb   = (unsigned char*)(sm);
    unsigned char* V2b  = (unsigned char*)(sm + 128);
    uint32_t*      PW2w = (uint32_t*)(sm + 16384);
    uint32_t*      PW3w = (uint32_t*)(sm + 18432);
    uint32_t*      W0w  = (uint32_t*)(sm + 26624);
    uint32_t*      PW1w = (uint32_t*)(sm + 26640);
    signed char*   DW1  = (signed char*)(sm + 26768);
    signed char*   DW2  = (signed char*)(sm + 26800);
    signed char*   DW3  = (signed char*)(sm + 27088);

    // ---- stage packed weights (L2-hot) + input quant/pack ----
    for (int i = tid; i < 512;  i += THREADS) PW2w[i] = gPW2[i];
    for (int i = tid; i < 2048; i += THREADS) PW3w[i] = gPW3[i];
    if (tid < 3)  W0w[tid]  = gW0[tid];
    if (tid < 32) PW1w[tid] = gPW1[tid];
    if (tid < 27) DW1[tid]  = gDW1[tid];
    for (int i = tid; i < 288; i += THREADS) DW2[i] = gDW2[i];
    for (int i = tid; i < 576; i += THREADS) DW3[i] = gDW3[i];

    const float* xin = x + (size_t)b * 3072;
    for (int p = tid; p < 1024; p += THREADS) {
        A4[p] = pack4(qa8c(xin[p]), qa8c(xin[1024 + p]), qa8c(xin[2048 + p]), 0);
    }
    __syncthreads();

    // ---- conv0: 1x1, 3->3, 8-bit ; requant to act4 codes ----
    for (int p = tid; p < 1024; p += THREADS) {
        int a = (int)A4[p];
        #pragma unroll
        for (int oc = 0; oc < 3; oc++) {
            int S = __dp4a(a, (int)W0w[oc], 0);
            B[oc * 1024 + p] = (signed char)clampi(rq5(S), -8, 7);
        }
    }
    __syncthreads();

    // ---- dw1: depthwise 3x3, 3ch @32x32 -> packed word per pixel ----
    for (int p = tid; p < 1024; p += THREADS) {
        int y = p >> 5, xx = p & 31;
        uint32_t w = 0;
        #pragma unroll
        for (int c = 0; c < 3; c++) {
            int S = 0;
            #pragma unroll
            for (int ky = 0; ky < 3; ky++) {
                int yy = y + ky - 1; if ((unsigned)yy > 31u) continue;
                #pragma unroll
                for (int kx = 0; kx < 3; kx++) {
                    int xc = xx + kx - 1; if ((unsigned)xc > 31u) continue;
                    S += (int)B[c * 1024 + yy * 32 + xc] * (int)DW1[c * 9 + ky * 3 + kx];
                }
            }
            w |= (uint32_t)(clampi(rq2(S), -8, 7) & 0xFF) << (8 * c);
        }
        P1[p] = w;
    }
    __syncthreads();

    // ---- pw1 (3->32) + QuantReLU + maxpool2 + act4 requant, fused ----
    for (int i = tid; i < 8192; i += THREADS) {
        int oc = i >> 8, pp = i & 255;
        int base = ((pp >> 4) * 2) * 32 + (pp & 15) * 2;
        int wv = (int)PW1w[oc];
        int s0 = __dp4a((int)P1[base],      wv, 0);
        int s1 = __dp4a((int)P1[base + 1],  wv, 0);
        int s2 = __dp4a((int)P1[base + 32], wv, 0);
        int s3 = __dp4a((int)P1[base + 33], wv, 0);
        int m = max(max(s0, s1), max(s2, s3));     // relucode monotone => pool raw accum
        D[i] = (signed char)c2a4(reluc(m));
    }
    __syncthreads();

    // ---- dw2: depthwise 3x3, 32ch @16x16 -> P2 packed quad-order [g][qidx] ----
    for (int i = tid; i < 8192; i += THREADS) {
        int c = i >> 8, p = i & 255, y = p >> 4, xx = p & 15;
        const signed char* dp = D + c * 256;
        const signed char* wp = DW2 + c * 9;
        int S = 0;
        #pragma unroll
        for (int ky = 0; ky < 3; ky++) {
            int yy = y + ky - 1; if ((unsigned)yy > 15u) continue;
            #pragma unroll
            for (int kx = 0; kx < 3; kx++) {
                int xc = xx + kx - 1; if ((unsigned)xc > 15u) continue;
                S += (int)dp[yy * 16 + xc] * (int)wp[ky * 3 + kx];
            }
        }
        int qidx = ((y >> 1) * 8 + (xx >> 1)) * 4 + (y & 1) * 2 + (xx & 1);
        ((signed char*)P2)[((c >> 2) * 256 + qidx) * 4 + (c & 3)] =
            (signed char)clampi(rq2(S), -8, 7);
    }
    __syncthreads();

    // ---- pw2 (32->64) + relu + maxpool2 + requant. 4oc x 1 pooled px (4 quads) ----
    for (int t2 = tid; t2 < 1024; t2 += THREADS) {
        int px = t2 & 63, oc0 = (t2 >> 6) * 4;
        int acc[4][4] = {};
        #pragma unroll
        for (int g = 0; g < 8; g++) {
            uint4 a = *(const uint4*)(P2 + g * 256 + px * 4);
            #pragma unroll
            for (int i2 = 0; i2 < 4; i2++) {
                int wv = (int)PW2w[(oc0 + i2) * 8 + g];
                acc[i2][0] = __dp4a((int)a.x, wv, acc[i2][0]);
                acc[i2][1] = __dp4a((int)a.y, wv, acc[i2][1]);
                acc[i2][2] = __dp4a((int)a.z, wv, acc[i2][2]);
                acc[i2][3] = __dp4a((int)a.w, wv, acc[i2][3]);
            }
        }
        #pragma unroll
        for (int i2 = 0; i2 < 4; i2++) {
            int m = max(max(acc[i2][0], acc[i2][1]), max(acc[i2][2], acc[i2][3]));
            D3[(oc0 + i2) * 64 + px] = (signed char)c2a4(reluc(m));
        }
    }
    __syncthreads();

    // ---- dw3: depthwise 3x3, 64ch @8x8 -> P3 packed [g][p] ----
    for (int i = tid; i < 4096; i += THREADS) {
        int c = i >> 6, p = i & 63, y = p >> 3, xx = p & 7;
        const signed char* dp = D3 + c * 64;
        const signed char* wp = DW3 + c * 9;
        int S = 0;
        #pragma unroll
        for (int ky = 0; ky < 3; ky++) {
            int yy = y + ky - 1; if ((unsigned)yy > 7u) continue;
            #pragma unroll
            for (int kx = 0; kx < 3; kx++) {
                int xc = xx + kx - 1; if ((unsigned)xc > 7u) continue;
                S += (int)dp[yy * 8 + xc] * (int)wp[ky * 3 + kx];
            }
        }
        ((signed char*)P3)[((c >> 2) * 64 + p) * 4 + (c & 3)] =
            (signed char)clampi(rq2(S), -8, 7);
    }
    __syncthreads();

    // ---- pw3 (64->128) + relu codes. 4oc x 4px blocking ----
    for (int t2 = tid; t2 < 512; t2 += THREADS) {
        int p0 = (t2 & 15) * 4, oc0 = (t2 >> 4) * 4;
        int acc[4][4] = {};
        #pragma unroll
        for (int g = 0; g < 16; g++) {
            uint4 a = *(const uint4*)(P3 + g * 64 + p0);
            #pragma unroll
            for (int i2 = 0; i2 < 4; i2++) {
                int wv = (int)PW3w[(oc0 + i2) * 16 + g];
                acc[i2][0] = __dp4a((int)a.x, wv, acc[i2][0]);
                acc[i2][1] = __dp4a((int)a.y, wv, acc[i2][1]);
                acc[i2][2] = __dp4a((int)a.z, wv, acc[i2][2]);
                acc[i2][3] = __dp4a((int)a.w, wv, acc[i2][3]);
            }
        }
        #pragma unroll
        for (int i2 = 0; i2 < 4; i2++)
            #pragma unroll
            for (int j = 0; j < 4; j++)
                K[(oc0 + i2) * 64 + p0 + j] = (unsigned char)reluc(acc[i2][j]);
    }
    __syncthreads();

    // ---- global maxpool 8x8 (SIMD byte max) + classifier input quant ----
    if (tid < 128) {
        const uint32_t* kp = (const uint32_t*)(K + tid * 64);
        uint32_t m = 0;
        #pragma unroll
        for (int i = 0; i < 16; i++) m = __vmaxu4(m, kp[i]);
        int mb = max(max((int)(m & 255), (int)((m >> 8) & 255)),
                     max((int)((m >> 16) & 255), (int)(m >> 24)));
        Vb[tid] = (unsigned char)c2a4(mb);
    }
    __syncthreads();

    // ---- fc1: 128->256 (weights streamed from global, coalesced) ----
    {
        const uint32_t* Vw = (const uint32_t*)Vb;
        int S = 0;
        #pragma unroll 8
        for (int g = 0; g < 32; g++)
            S = __dp4a((int)Vw[g], (int)gFC1[g * 256 + tid], S);
        V2b[tid] = (unsigned char)c2a4(reluc(S));
    }
    __syncthreads();

    // ---- fc2: 256->10, output int8 quant (o = S*0.125 -> round(o*16)=2S) ----
    if (tid < 160) {
        int oc = tid >> 4, l = tid & 15;
        const uint32_t* Vw = (const uint32_t*)V2b;
        int S = 0;
        #pragma unroll
        for (int k = 0; k < 4; k++) {
            int g = l + k * 16;
            S = __dp4a((int)Vw[g], (int)gFC2[oc * 64 + g], S);
        }
        #pragma unroll
        for (int off = 8; off; off >>= 1) S += __shfl_down_sync(0xffffffffu, S, off, 16);
        if (l == 0) {
            int o = clampi(2 * S, -128, 127);
            out[(size_t)b * 10 + oc] = (float)o * 0.0625f;
        }
    }
}

extern "C" void kernel_launch(void* const* d_in, const int* in_sizes, int n_in,
                              void* d_out, int out_size)
{
    (void)in_sizes; (void)n_in; (void)out_size;
    const float* x   = (const float*)d_in[0];
    const float* w0  = (const float*)d_in[1];
    const float* dw1 = (const float*)d_in[2];
    const float* pw1 = (const float*)d_in[3];
    const float* dw2 = (const float*)d_in[4];
    const float* pw2 = (const float*)d_in[5];
    const float* dw3 = (const float*)d_in[6];
    const float* pw3 = (const float*)d_in[7];
    const float* wc1 = (const float*)d_in[8];
    const float* wc2 = (const float*)d_in[9];
    float* out = (float*)d_out;

    prep_kernel<<<48, THREADS>>>(w0, dw1, pw1, dw2, pw2, dw3, pw3, wc1, wc2);
    qnet_kernel<<<1024, THREADS, SM_BYTES>>>(x, out);
}

// round 3
// speedup vs baseline: 5.7395x; 1.3456x over previous
#include <cuda_runtime.h>
#include <cstdint>

// Fully fused quantized CIFAR-10 net, integer/DP4A datapath, vectorized depthwise.
// Prep kernel quantizes+packs weights once into __device__ globals; main kernel:
// one CTA per image, intermediates as int8 codes in SMEM (x-packed per channel for
// depthwise, channel-packed for pointwise). Integer round-half-even == jnp.round.

#define THREADS 256

// ---------------- packed weight globals (written by prep_kernel) ----------------
__device__ uint32_t gW0[4];      // conv0 [oc<3]: (3 x int8 code, 0)
__device__ uint32_t gPW1[32];    // pw1 [oc]: (3 ic codes, 0)
__device__ uint32_t gPW2[512];   // pw2 [oc*8+g]: 4 ic codes
__device__ uint32_t gPW3[2048];  // pw3 [oc*16+g]: 4 ic codes
__device__ uint32_t gFC1[8192];  // fc1 [g*256+oc]: 4 ic codes (coalesced by oc)
__device__ uint32_t gFC2[640];   // fc2 [oc*64+g]: 4 ic codes
__device__ uint32_t gDW1r[16];   // dw1 row-packed [c*3+ky] = (w0,w1,w2,0), 9 used
__device__ uint32_t gDW2r[96];   // dw2 row-packed [c*3+ky]
__device__ uint32_t gDW3r[192];  // dw3 row-packed [c*3+ky]

// ---------------- helpers ----------------
__device__ __forceinline__ int clampi(int v, int lo, int hi) { return min(max(v, lo), hi); }
__device__ __forceinline__ uint32_t pack4(int a, int b, int c, int d) {
    return (uint32_t)(a & 0xFF) | ((uint32_t)(b & 0xFF) << 8) |
           ((uint32_t)(c & 0xFF) << 16) | ((uint32_t)(d & 0xFF) << 24);
}
__device__ __forceinline__ int qw4c(float w) {
    float q = rintf(w * 4.f); return (int)fmaxf(-8.f, fminf(7.f, q));
}
__device__ __forceinline__ int qw8c(float w) {
    float q = rintf(w * 4.f); return (int)fmaxf(-128.f, fminf(127.f, q));
}
__device__ __forceinline__ int qa8c(float v) {
    float q = rintf(v * 16.f); return (int)fmaxf(-128.f, fminf(127.f, q));
}
// round-half-even of S/4 (act4 requant after dw/pw: round(S*0.25))
__device__ __forceinline__ int rq2(int S) {
    int q = S >> 2, r = S & 3; return q + (r > 2) + ((r == 2) & (q & 1));
}
// round-half-even of S/32 (conv0 act4 requant)
__device__ __forceinline__ int rq5(int S) {
    int q = S >> 5, r = S & 31; return q + (r > 16) + ((r == 16) & (q & 1));
}
// QuantReLU4 code from raw accum (o = S*0.125, code = round(o*4) clip [0,15])
__device__ __forceinline__ int reluc(int S) {
    int m = max(S, 0); int k = m >> 1; k += (k & m & 1); return min(k, 15);
}
// relu code (val c*0.25) -> S_ACT4 signed 4-bit code (round(c*0.5) clip 7)
__device__ __forceinline__ int c2a4(int c) {
    int k = c >> 1; k += (k & c & 1); return min(k, 7);
}

// ---------------- prep: quantize + pack weights ----------------
__global__ void prep_kernel(const float* __restrict__ w0,  const float* __restrict__ dw1,
                            const float* __restrict__ pw1, const float* __restrict__ dw2,
                            const float* __restrict__ pw2, const float* __restrict__ dw3,
                            const float* __restrict__ pw3, const float* __restrict__ wc1,
                            const float* __restrict__ wc2)
{
    int t = blockIdx.x * blockDim.x + threadIdx.x;
    int NT = gridDim.x * blockDim.x;
    for (int i = t; i < 3; i += NT)
        gW0[i] = pack4(qw8c(w0[i*3]), qw8c(w0[i*3+1]), qw8c(w0[i*3+2]), 0);
    for (int i = t; i < 32; i += NT)
        gPW1[i] = pack4(qw4c(pw1[i*3]), qw4c(pw1[i*3+1]), qw4c(pw1[i*3+2]), 0);
    for (int i = t; i < 512; i += NT) {
        int oc = i >> 3, g = i & 7; const float* p = pw2 + oc*32 + g*4;
        gPW2[i] = pack4(qw4c(p[0]), qw4c(p[1]), qw4c(p[2]), qw4c(p[3]));
    }
    for (int i = t; i < 2048; i += NT) {
        int oc = i >> 4, g = i & 15; const float* p = pw3 + oc*64 + g*4;
        gPW3[i] = pack4(qw4c(p[0]), qw4c(p[1]), qw4c(p[2]), qw4c(p[3]));
    }
    for (int i = t; i < 8192; i += NT) {
        int g = i >> 8, oc = i & 255; const float* p = wc1 + oc*128 + g*4;
        gFC1[i] = pack4(qw4c(p[0]), qw4c(p[1]), qw4c(p[2]), qw4c(p[3]));
    }
    for (int i = t; i < 640; i += NT) {
        int oc = i / 64, g = i & 63; const float* p = wc2 + oc*256 + g*4;
        gFC2[i] = pack4(qw4c(p[0]), qw4c(p[1]), qw4c(p[2]), qw4c(p[3]));
    }
    for (int i = t; i < 9; i += NT) {
        int c = i / 3, ky = i % 3; const float* p = dw1 + c*9 + ky*3;
        gDW1r[i] = pack4(qw4c(p[0]), qw4c(p[1]), qw4c(p[2]), 0);
    }
    for (int i = t; i < 96; i += NT) {
        int c = i / 3, ky = i % 3; const float* p = dw2 + c*9 + ky*3;
        gDW2r[i] = pack4(qw4c(p[0]), qw4c(p[1]), qw4c(p[2]), 0);
    }
    for (int i = t; i < 192; i += NT) {
        int c = i / 3, ky = i % 3; const float* p = dw3 + c*9 + ky*3;
        gDW3r[i] = pack4(qw4c(p[0]), qw4c(p[1]), qw4c(p[2]), 0);
    }
}

// ---------------- main fused kernel ----------------
// SMEM (27968 B): R0 [0,8192) / R1 [8192,16384) alternate stage buffers.
//  PW2w [16384,18432) PW3w [18432,26624) PW1w [26624,26752)
//  DW1r [26752,26792) DW2r [26792,27176) DW3r [27176,27944)
#define SM_BYTES 27968

__global__ __launch_bounds__(THREADS, 5)
void qnet_kernel(const float* __restrict__ x, float* __restrict__ out)
{
    extern __shared__ unsigned char sm[];
    const int tid = threadIdx.x;
    const int b   = blockIdx.x;

    signed char*   B    = (signed char*)(sm);           // conv0 out [c][1024], x-packed
    uint32_t*      P1   = (uint32_t*)(sm + 8192);       // dw1 out, pixel-packed 3ch words
    signed char*   D    = (signed char*)(sm);           // pw1 out [oc][256], x-packed
    uint32_t*      P2   = (uint32_t*)(sm + 8192);       // dw2 out [g][qidx] 4ch words
    signed char*   D3   = (signed char*)(sm);           // pw2 out [oc][64], x-packed
    uint32_t*      P3   = (uint32_t*)(sm + 8192);       // dw3 out [g][p] 4ch words
    unsigned char* K    = (unsigned char*)(sm);         // pw3 relu codes [oc][64]
    unsigned char* Vb   = (unsigned char*)(sm + 8192);  // 128
    unsigned char* V2b  = (unsigned char*)(sm + 8320);  // 256
    uint32_t*      PW2w = (uint32_t*)(sm + 16384);
    uint32_t*      PW3w = (uint32_t*)(sm + 18432);
    uint32_t*      PW1w = (uint32_t*)(sm + 26624);
    uint32_t*      DW1r = (uint32_t*)(sm + 26752);
    uint32_t*      DW2r = (uint32_t*)(sm + 26792);
    uint32_t*      DW3r = (uint32_t*)(sm + 27176);

    // ---- stage packed weights (L2-hot) ----
    for (int i = tid; i < 512;  i += THREADS) PW2w[i] = gPW2[i];
    for (int i = tid; i < 2048; i += THREADS) PW3w[i] = gPW3[i];
    if (tid < 32)  PW1w[tid] = gPW1[tid];
    if (tid < 9)   DW1r[tid] = gDW1r[tid];
    if (tid < 96)  DW2r[tid] = gDW2r[tid];
    if (tid < 192) DW3r[tid] = gDW3r[tid];

    // ---- input load + 8-bit quant + conv0 (1x1, 3->3) + act4 requant, fused ----
    {
        const float* xin = x + (size_t)b * 3072;
        int w00 = (int)gW0[0], w01 = (int)gW0[1], w02 = (int)gW0[2];
        #pragma unroll
        for (int k = 0; k < 4; k++) {
            int p = tid + k * 256;
            int a = (int)pack4(qa8c(xin[p]), qa8c(xin[1024 + p]), qa8c(xin[2048 + p]), 0);
            B[p]        = (signed char)clampi(rq5(__dp4a(a, w00, 0)), -8, 7);
            B[1024 + p] = (signed char)clampi(rq5(__dp4a(a, w01, 0)), -8, 7);
            B[2048 + p] = (signed char)clampi(rq5(__dp4a(a, w02, 0)), -8, 7);
        }
    }
    __syncthreads();

    // ---- dw1: depthwise 3x3, 3ch @32x32. Thread = 1 word (4 px), all 3 ch ----
    {
        int y = tid >> 3, wx = tid & 7;
        int res[3][4];
        #pragma unroll
        for (int c = 0; c < 3; c++) {
            int a0 = 0, a1 = 0, a2 = 0, a3 = 0;
            #pragma unroll
            for (int ky = 0; ky < 3; ky++) {
                int yy = y + ky - 1;
                if ((unsigned)yy <= 31u) {
                    const uint32_t* rp = (const uint32_t*)(B + c * 1024 + yy * 32);
                    uint32_t cur  = rp[wx];
                    uint32_t prev = wx ? rp[wx - 1] : 0u;
                    uint32_t nxt  = (wx < 7) ? rp[wx + 1] : 0u;
                    int wv = (int)DW1r[c * 3 + ky];
                    a0 = __dp4a((int)__byte_perm(cur, prev, 0x0107), wv, a0);
                    a1 = __dp4a((int)cur,                            wv, a1);
                    a2 = __dp4a((int)(cur >> 8),                     wv, a2);
                    a3 = __dp4a((int)__byte_perm(cur, nxt, 0x0432),  wv, a3);
                }
            }
            res[c][0] = clampi(rq2(a0), -8, 7);
            res[c][1] = clampi(rq2(a1), -8, 7);
            res[c][2] = clampi(rq2(a2), -8, 7);
            res[c][3] = clampi(rq2(a3), -8, 7);
        }
        uint4 o;
        o.x = pack4(res[0][0], res[1][0], res[2][0], 0);
        o.y = pack4(res[0][1], res[1][1], res[2][1], 0);
        o.z = pack4(res[0][2], res[1][2], res[2][2], 0);
        o.w = pack4(res[0][3], res[1][3], res[2][3], 0);
        *(uint4*)(P1 + y * 32 + wx * 4) = o;
    }
    __syncthreads();

    // ---- pw1 (3->32) + relu + maxpool2 + act4 requant. Thread = 1 pooled px ----
    {
        int y = tid >> 4, xx = tid & 15;
        int base = (y * 2) * 32 + xx * 2;
        int q0 = (int)P1[base],      q1 = (int)P1[base + 1];
        int q2 = (int)P1[base + 32], q3 = (int)P1[base + 33];
        #pragma unroll
        for (int oc = 0; oc < 32; oc++) {
            int wv = (int)PW1w[oc];
            int s0 = __dp4a(q0, wv, 0), s1 = __dp4a(q1, wv, 0);
            int s2 = __dp4a(q2, wv, 0), s3 = __dp4a(q3, wv, 0);
            int m = max(max(s0, s1), max(s2, s3));
            D[oc * 256 + tid] = (signed char)c2a4(reluc(m));
        }
    }
    __syncthreads();

    // ---- dw2: depthwise 3x3, 32ch @16x16. Thread-item = 1 word (4 px) of 1 ch ----
    #pragma unroll
    for (int k = 0; k < 8; k++) {
        int item = tid + k * 256;
        int c = item >> 6, w = item & 63;
        int y = w >> 2, wx = w & 3;
        const uint32_t* chb = (const uint32_t*)(D + c * 256);
        int a0 = 0, a1 = 0, a2 = 0, a3 = 0;
        #pragma unroll
        for (int ky = 0; ky < 3; ky++) {
            int yy = y + ky - 1;
            if ((unsigned)yy <= 15u) {
                const uint32_t* rp = chb + yy * 4;
                uint32_t cur  = rp[wx];
                uint32_t prev = wx ? rp[wx - 1] : 0u;
                uint32_t nxt  = (wx < 3) ? rp[wx + 1] : 0u;
                int wv = (int)DW2r[c * 3 + ky];
                a0 = __dp4a((int)__byte_perm(cur, prev, 0x0107), wv, a0);
                a1 = __dp4a((int)cur,                            wv, a1);
                a2 = __dp4a((int)(cur >> 8),                     wv, a2);
                a3 = __dp4a((int)__byte_perm(cur, nxt, 0x0432),  wv, a3);
            }
        }
        int g = c >> 2, lane = c & 3;
        int acc[4] = {a0, a1, a2, a3};
        #pragma unroll
        for (int j = 0; j < 4; j++) {
            int ppx = (y >> 1) * 8 + wx * 2 + (j >> 1);
            int member = (y & 1) * 2 + (j & 1);
            ((signed char*)P2)[(g * 256 + ppx * 4 + member) * 4 + lane] =
                (signed char)clampi(rq2(acc[j]), -8, 7);
        }
    }
    __syncthreads();

    // ---- pw2 (32->64) + relu + maxpool2 + requant. 4oc x 1 pooled px ----
    #pragma unroll
    for (int k = 0; k < 4; k++) {
        int t2 = tid + k * 256;
        int px = t2 & 63, oc0 = (t2 >> 6) * 4;
        int acc[4][4] = {};
        #pragma unroll
        for (int g = 0; g < 8; g++) {
            uint4 a = *(const uint4*)(P2 + g * 256 + px * 4);
            #pragma unroll
            for (int i2 = 0; i2 < 4; i2++) {
                int wv = (int)PW2w[(oc0 + i2) * 8 + g];
                acc[i2][0] = __dp4a((int)a.x, wv, acc[i2][0]);
                acc[i2][1] = __dp4a((int)a.y, wv, acc[i2][1]);
                acc[i2][2] = __dp4a((int)a.z, wv, acc[i2][2]);
                acc[i2][3] = __dp4a((int)a.w, wv, acc[i2][3]);
            }
        }
        #pragma unroll
        for (int i2 = 0; i2 < 4; i2++) {
            int m = max(max(acc[i2][0], acc[i2][1]), max(acc[i2][2], acc[i2][3]));
            D3[(oc0 + i2) * 64 + px] = (signed char)c2a4(reluc(m));
        }
    }
    __syncthreads();

    // ---- dw3: depthwise 3x3, 64ch @8x8. Thread-item = 1 word (4 px) of 1 ch ----
    #pragma unroll
    for (int k = 0; k < 4; k++) {
        int item = tid + k * 256;
        int c = item >> 4, w = item & 15;
        int y = w >> 1, wx = w & 1;
        const uint32_t* chb = (const uint32_t*)(D3 + c * 64);
        int a0 = 0, a1 = 0, a2 = 0, a3 = 0;
        #pragma unroll
        for (int ky = 0; ky < 3; ky++) {
            int yy = y + ky - 1;
            if ((unsigned)yy <= 7u) {
                const uint32_t* rp = chb + yy * 2;
                uint32_t cur  = rp[wx];
                uint32_t prev = wx ? rp[0] : 0u;
                uint32_t nxt  = wx ? 0u : rp[1];
                int wv = (int)DW3r[c * 3 + ky];
                a0 = __dp4a((int)__byte_perm(cur, prev, 0x0107), wv, a0);
                a1 = __dp4a((int)cur,                            wv, a1);
                a2 = __dp4a((int)(cur >> 8),                     wv, a2);
                a3 = __dp4a((int)__byte_perm(cur, nxt, 0x0432),  wv, a3);
            }
        }
        int g = c >> 2, lane = c & 3;
        int p0 = y * 8 + wx * 4;
        int acc[4] = {a0, a1, a2, a3};
        #pragma unroll
        for (int j = 0; j < 4; j++)
            ((signed char*)P3)[(g * 64 + p0 + j) * 4 + lane] =
                (signed char)clampi(rq2(acc[j]), -8, 7);
    }
    __syncthreads();

    // ---- pw3 (64->128) + relu codes. 4oc x 4px blocking ----
    #pragma unroll
    for (int k = 0; k < 2; k++) {
        int t2 = tid + k * 256;
        int p0 = (t2 & 15) * 4, oc0 = (t2 >> 4) * 4;
        int acc[4][4] = {};
        #pragma unroll
        for (int g = 0; g < 16; g++) {
            uint4 a = *(const uint4*)(P3 + g * 64 + p0);
            #pragma unroll
            for (int i2 = 0; i2 < 4; i2++) {
                int wv = (int)PW3w[(oc0 + i2) * 16 + g];
                acc[i2][0] = __dp4a((int)a.x, wv, acc[i2][0]);
                acc[i2][1] = __dp4a((int)a.y, wv, acc[i2][1]);
                acc[i2][2] = __dp4a((int)a.z, wv, acc[i2][2]);
                acc[i2][3] = __dp4a((int)a.w, wv, acc[i2][3]);
            }
        }
        #pragma unroll
        for (int i2 = 0; i2 < 4; i2++)
            #pragma unroll
            for (int j = 0; j < 4; j++)
                K[(oc0 + i2) * 64 + p0 + j] = (unsigned char)reluc(acc[i2][j]);
    }
    __syncthreads();

    // ---- global maxpool 8x8 (SIMD byte max) + classifier input quant ----
    if (tid < 128) {
        const uint4* kp = (const uint4*)(K + tid * 64);
        uint32_t m = 0;
        #pragma unroll
        for (int i = 0; i < 4; i++) {
            uint4 v = kp[i];
            m = __vmaxu4(m, v.x); m = __vmaxu4(m, v.y);
            m = __vmaxu4(m, v.z); m = __vmaxu4(m, v.w);
        }
        int mb = max(max((int)(m & 255), (int)((m >> 8) & 255)),
                     max((int)((m >> 16) & 255), (int)(m >> 24)));
        Vb[tid] = (unsigned char)c2a4(mb);
    }
    __syncthreads();

    // ---- fc1: 128->256 (weights streamed from global, coalesced, L2-hot) ----
    {
        const uint32_t* Vw = (const uint32_t*)Vb;
        int S = 0;
        #pragma unroll 8
        for (int g = 0; g < 32; g++)
            S = __dp4a((int)Vw[g], (int)gFC1[g * 256 + tid], S);
        V2b[tid] = (unsigned char)c2a4(reluc(S));
    }
    __syncthreads();

    // ---- fc2: 256->10, output int8 quant (o = S*0.125 -> round(o*16) = 2S) ----
    if (tid < 160) {
        int oc = tid >> 4, l = tid & 15;
        const uint32_t* Vw = (const uint32_t*)V2b;
        int S = 0;
        #pragma unroll
        for (int k = 0; k < 4; k++) {
            int g = l + k * 16;
            S = __dp4a((int)Vw[g], (int)gFC2[oc * 64 + g], S);
        }
        #pragma unroll
        for (int off = 8; off; off >>= 1) S += __shfl_down_sync(0xffffffffu, S, off, 16);
        if (l == 0) {
            int o = clampi(2 * S, -128, 127);
            out[(size_t)b * 10 + oc] = (float)o * 0.0625f;
        }
    }
}

extern "C" void kernel_launch(void* const* d_in, const int* in_sizes, int n_in,
                              void* d_out, int out_size)
{
    (void)in_sizes; (void)n_in; (void)out_size;
    const float* x   = (const float*)d_in[0];
    const float* w0  = (const float*)d_in[1];
    const float* dw1 = (const float*)d_in[2];
    const float* pw1 = (const float*)d_in[3];
    const float* dw2 = (const float*)d_in[4];
    const float* pw2 = (const float*)d_in[5];
    const float* dw3 = (const float*)d_in[6];
    const float* pw3 = (const float*)d_in[7];
    const float* wc1 = (const float*)d_in[8];
    const float* wc2 = (const float*)d_in[9];
    float* out = (float*)d_out;

    prep_kernel<<<48, THREADS>>>(w0, dw1, pw1, dw2, pw2, dw3, pw3, wc1, wc2);
    qnet_kernel<<<1024, THREADS, SM_BYTES>>>(x, out);
}